// round 6
// baseline (speedup 1.0000x reference)
#include <cuda_runtime.h>
#include <cuda_bf16.h>
#include <cuda_fp16.h>

#define B_  4
#define N_  2048
#define M_  2048
#define H_  16
#define D_  64
#define E_  1024

__device__ float g_Q[(size_t)B_ * H_ * N_ * D_];
__device__ float g_K[(size_t)B_ * H_ * M_ * D_];
__device__ float g_V[(size_t)B_ * H_ * M_ * D_];
__device__ float g_AO[(size_t)B_ * N_ * E_];

// ---------------------------------------------------------------------------
// helpers
// ---------------------------------------------------------------------------
__device__ __forceinline__ float ex2f_(float x) {
    float y; asm("ex2.approx.f32 %0, %1;" : "=f"(y) : "f"(x)); return y;
}
// bf16 m16n8k16
__device__ __forceinline__ void mma16(float* d, const unsigned* a, unsigned b0, unsigned b1) {
    asm("mma.sync.aligned.m16n8k16.row.col.f32.bf16.bf16.f32 "
        "{%0,%1,%2,%3},{%4,%5,%6,%7},{%8,%9},{%0,%1,%2,%3};"
        : "+f"(d[0]), "+f"(d[1]), "+f"(d[2]), "+f"(d[3])
        : "r"(a[0]), "r"(a[1]), "r"(a[2]), "r"(a[3]), "r"(b0), "r"(b1));
}
// fp16 m16n8k16
__device__ __forceinline__ void mma16h(float* d, const unsigned* a, unsigned b0, unsigned b1) {
    asm("mma.sync.aligned.m16n8k16.row.col.f32.f16.f16.f32 "
        "{%0,%1,%2,%3},{%4,%5,%6,%7},{%8,%9},{%0,%1,%2,%3};"
        : "+f"(d[0]), "+f"(d[1]), "+f"(d[2]), "+f"(d[3])
        : "r"(a[0]), "r"(a[1]), "r"(a[2]), "r"(a[3]), "r"(b0), "r"(b1));
}
// pack two fp32 -> f16x2 (first arg -> low half = even element)
__device__ __forceinline__ unsigned packh(float lo, float hi) {
    unsigned r; asm("cvt.rn.f16x2.f32 %0, %1, %2;" : "=r"(r) : "f"(hi), "f"(lo)); return r;
}
__device__ __forceinline__ void ldsm4(unsigned* r, unsigned addr) {
    asm volatile("ldmatrix.sync.aligned.m8n8.x4.shared.b16 {%0,%1,%2,%3}, [%4];"
                 : "=r"(r[0]), "=r"(r[1]), "=r"(r[2]), "=r"(r[3]) : "r"(addr));
}
__device__ __forceinline__ void ldsm4t(unsigned* r, unsigned addr) {
    asm volatile("ldmatrix.sync.aligned.m8n8.x4.trans.shared.b16 {%0,%1,%2,%3}, [%4];"
                 : "=r"(r[0]), "=r"(r[1]), "=r"(r[2]), "=r"(r[3]) : "r"(addr));
}

// ---------------------------------------------------------------------------
// Split-bf16 GEMM: Y = X (R x 1024) @ W^T (+bias). acc += hA*hB + hA*lB + lA*hB
// Block 128x128, 8 warps (2x4), warp tile 64x32, K-chunks of 16.
// smem: bf16 pairs (u32), row stride 12 u32 (48B); DOUBLE-BUFFERED (2x24KB);
// fragments loaded via ldmatrix.x4 (rows at 12r words mod 32 cover all banks).
// ---------------------------------------------------------------------------
#define GP 12
__global__ __launch_bounds__(256) void gemm_tc(
    const float* __restrict__ X, const float* __restrict__ W,
    float* __restrict__ Y, const float* __restrict__ bias, int mode)
{
    __shared__ unsigned Ahi[2][128 * GP], Alo[2][128 * GP];
    __shared__ unsigned Bhi[2][128 * GP], Blo[2][128 * GP];

    const int tid = threadIdx.x, lane = tid & 31, warp = tid >> 5;
    const int g = lane >> 2, tg = lane & 3;
    const int wm = (warp >> 2) * 64, wn = (warp & 3) * 32;
    const int m0 = blockIdx.y * 128, n0 = blockIdx.x * 128;

    const int sr = tid >> 2;
    const int sc = (tid & 3) * 4;     // float offset
    const int pc = (tid & 3) * 2;     // pair offset
    const float* Ap = X + (size_t)(m0 + sr) * E_ + sc;
    const float* Bp = W + (size_t)(n0 + sr) * E_ + sc;

    // ldmatrix lane geometry: row-within-16 and k-half
    const int lrow = ((lane >> 3) & 1) * 8 + (lane & 7);
    const int lkh  = lane >> 4;
    const unsigned ahi0 = (unsigned)__cvta_generic_to_shared(Ahi);
    const unsigned alo0 = (unsigned)__cvta_generic_to_shared(Alo);
    const unsigned bhi0 = (unsigned)__cvta_generic_to_shared(Bhi);
    const unsigned blo0 = (unsigned)__cvta_generic_to_shared(Blo);
    const unsigned aoff = (unsigned)((wm + lrow) * 48 + lkh * 16);
    const unsigned boff = (unsigned)((wn + lrow) * 48 + lkh * 16);

    float acc[4][4][4];
#pragma unroll
    for (int i = 0; i < 4; ++i)
#pragma unroll
        for (int j = 0; j < 4; ++j)
#pragma unroll
            for (int k = 0; k < 4; ++k) acc[i][j][k] = 0.f;

    auto splitstore = [&](unsigned* Hi, unsigned* Lo, int idx, float4 v) {
        __nv_bfloat162 h01 = __floats2bfloat162_rn(v.x, v.y);
        __nv_bfloat162 h23 = __floats2bfloat162_rn(v.z, v.w);
        float r0 = v.x - __bfloat162float(h01.x);
        float r1 = v.y - __bfloat162float(h01.y);
        float r2 = v.z - __bfloat162float(h23.x);
        float r3 = v.w - __bfloat162float(h23.y);
        __nv_bfloat162 l01 = __floats2bfloat162_rn(r0, r1);
        __nv_bfloat162 l23 = __floats2bfloat162_rn(r2, r3);
        uint2 hu, lu;
        hu.x = *(unsigned*)&h01; hu.y = *(unsigned*)&h23;
        lu.x = *(unsigned*)&l01; lu.y = *(unsigned*)&l23;
        *(uint2*)&Hi[idx] = hu;
        *(uint2*)&Lo[idx] = lu;
    };

    // stage chunk 0 into buffer 0
    splitstore(Ahi[0], Alo[0], sr * GP + pc,        *(const float4*)Ap);
    splitstore(Ahi[0], Alo[0], (sr + 64) * GP + pc, *(const float4*)(Ap + (size_t)64 * E_));
    splitstore(Bhi[0], Blo[0], sr * GP + pc,        *(const float4*)Bp);
    splitstore(Bhi[0], Blo[0], (sr + 64) * GP + pc, *(const float4*)(Bp + (size_t)64 * E_));
    __syncthreads();

    float4 pa0, pa1, pb0, pb1;
    for (int c = 0; c < 64; ++c) {
        const int bs = c & 1;
        const unsigned bufo = (unsigned)bs * (128 * GP * 4);
        if (c < 63) {
            const float* A2 = Ap + (c + 1) * 16;
            const float* B2 = Bp + (c + 1) * 16;
            pa0 = *(const float4*)A2;
            pa1 = *(const float4*)(A2 + (size_t)64 * E_);
            pb0 = *(const float4*)B2;
            pb1 = *(const float4*)(B2 + (size_t)64 * E_);
        }
        unsigned ah[4][4], al[4][4], bh[2][4], bl[2][4];
#pragma unroll
        for (int mt = 0; mt < 4; ++mt) {
            unsigned o_ = bufo + aoff + (unsigned)mt * 768u;
            ldsm4(ah[mt], ahi0 + o_);
            ldsm4(al[mt], alo0 + o_);
        }
#pragma unroll
        for (int p = 0; p < 2; ++p) {
            unsigned o_ = bufo + boff + (unsigned)p * 768u;
            ldsm4(bh[p], bhi0 + o_);
            ldsm4(bl[p], blo0 + o_);
        }
#pragma unroll
        for (int mt = 0; mt < 4; ++mt)
#pragma unroll
            for (int nt = 0; nt < 4; ++nt) {
                const int p = nt >> 1, sel = nt & 1;
                mma16(acc[mt][nt], ah[mt], bh[p][sel], bh[p][sel + 2]);   // hi*hi
                mma16(acc[mt][nt], ah[mt], bl[p][sel], bl[p][sel + 2]);   // hi*lo
                mma16(acc[mt][nt], al[mt], bh[p][sel], bh[p][sel + 2]);   // lo*hi
            }
        if (c < 63) {
            const int nb = bs ^ 1;
            splitstore(Ahi[nb], Alo[nb], sr * GP + pc,        pa0);
            splitstore(Ahi[nb], Alo[nb], (sr + 64) * GP + pc, pa1);
            splitstore(Bhi[nb], Blo[nb], sr * GP + pc,        pb0);
            splitstore(Bhi[nb], Blo[nb], (sr + 64) * GP + pc, pb1);
            __syncthreads();
        }
    }

    if (mode == 0) {
#pragma unroll
        for (int mt = 0; mt < 4; ++mt) {
            int m = m0 + wm + mt * 16 + g;
            int bi = m >> 11, n = m & 2047;
#pragma unroll
            for (int nt = 0; nt < 4; ++nt) {
                int o = n0 + wn + nt * 8 + 2 * tg;
                int h = o >> 6, d = o & 63;
                *(float2*)&Y[(((size_t)(bi * H_ + h)) * 2048 + n) * D_ + d] =
                    make_float2(acc[mt][nt][0], acc[mt][nt][1]);
                *(float2*)&Y[(((size_t)(bi * H_ + h)) * 2048 + n + 8) * D_ + d] =
                    make_float2(acc[mt][nt][2], acc[mt][nt][3]);
            }
        }
    } else {
#pragma unroll
        for (int mt = 0; mt < 4; ++mt) {
            int m = m0 + wm + mt * 16 + g;
#pragma unroll
            for (int nt = 0; nt < 4; ++nt) {
                int o = n0 + wn + nt * 8 + 2 * tg;
                float bx = bias[o], by = bias[o + 1];
                *(float2*)&Y[(size_t)m * E_ + o] =
                    make_float2(acc[mt][nt][0] + bx, acc[mt][nt][1] + by);
                *(float2*)&Y[(size_t)(m + 8) * E_ + o] =
                    make_float2(acc[mt][nt][2] + bx, acc[mt][nt][3] + by);
            }
        }
    }
}

// ---------------------------------------------------------------------------
// Attention: ALL fp16 tensor ops (fp16 mantissa == tf32 mantissa, so accuracy
// matches the tf32 version). QK^T via m16n8k16 with K B-frags from
// ldmatrix.x4; P@V reuses the S-register->A-frag identity (no shuffles);
// V frags via ldmatrix.x4.trans. K/V rows: 72 halves (144B) -> conflict-free.
// ---------------------------------------------------------------------------
#define KP 36   // u32 pairs per row
__global__ __launch_bounds__(256) void attn_tc()
{
    __shared__ unsigned Ks2[64 * KP];   // fp16 pairs [key][d/2]
    __shared__ unsigned Vs2[64 * KP];

    const int tid = threadIdx.x, lane = tid & 31, warp = tid >> 5;
    const int g = lane >> 2, tg = lane & 3;
    const int bh = blockIdx.y, q0 = blockIdx.x * 128;

    // Q A-fragments (fp16, scale*log2e folded), 4 chunks of k16 over d=64
    const float* Qg = g_Q + ((size_t)bh * N_ + q0 + warp * 16) * D_;
    const float qs = 0.125f * 1.4426950408889634f;
    unsigned qa[4][4];
#pragma unroll
    for (int c = 0; c < 4; ++c) {
        const float* r0 = Qg + g * 64 + c * 16;
        const float* r8 = Qg + (g + 8) * 64 + c * 16;
        qa[c][0] = packh(r0[2 * tg] * qs,     r0[2 * tg + 1] * qs);
        qa[c][1] = packh(r8[2 * tg] * qs,     r8[2 * tg + 1] * qs);
        qa[c][2] = packh(r0[2 * tg + 8] * qs, r0[2 * tg + 9] * qs);
        qa[c][3] = packh(r8[2 * tg + 8] * qs, r8[2 * tg + 9] * qs);
    }

    float o[8][4];
#pragma unroll
    for (int i = 0; i < 8; ++i)
#pragma unroll
        for (int j = 0; j < 4; ++j) o[i][j] = 0.f;
    float l0 = 0.f, l1 = 0.f;

    const float4* Kg = (const float4*)(g_K + (size_t)bh * M_ * D_);
    const float4* Vg = (const float4*)(g_V + (size_t)bh * M_ * D_);
    const unsigned kbase = (unsigned)__cvta_generic_to_shared(Ks2);
    const unsigned vbase = (unsigned)__cvta_generic_to_shared(Vs2);
    const int lrow = ((lane >> 3) & 1) * 8 + (lane & 7);
    const int lkh  = lane >> 4;

    for (int k0 = 0; k0 < M_; k0 += 64) {
        __syncthreads();
#pragma unroll
        for (int i = 0; i < 4; ++i) {
            int f4 = tid + i * 256;
            int row = f4 >> 4;
            int colp = (f4 & 15) * 2;          // pair index (even)
            float4 kv = Kg[k0 * 16 + f4];
            __half2 k01 = __floats2half2_rn(kv.x, kv.y);
            __half2 k23 = __floats2half2_rn(kv.z, kv.w);
            uint2 ku; ku.x = *(unsigned*)&k01; ku.y = *(unsigned*)&k23;
            *(uint2*)&Ks2[row * KP + colp] = ku;
            float4 vv = Vg[k0 * 16 + f4];
            __half2 v01 = __floats2half2_rn(vv.x, vv.y);
            __half2 v23 = __floats2half2_rn(vv.z, vv.w);
            uint2 vu; vu.x = *(unsigned*)&v01; vu.y = *(unsigned*)&v23;
            *(uint2*)&Vs2[row * KP + colp] = vu;
        }
        __syncthreads();

        // S = Q K^T (fp16 MMA, fp32 accum)
        float s[8][4];
#pragma unroll
        for (int nt = 0; nt < 8; ++nt)
#pragma unroll
            for (int j = 0; j < 4; ++j) s[nt][j] = 0.f;
#pragma unroll
        for (int c = 0; c < 4; ++c) {
#pragma unroll
            for (int p = 0; p < 4; ++p) {
                unsigned kb[4];
                ldsm4(kb, kbase + (unsigned)((p * 16 + lrow) * 144 + c * 32 + lkh * 16));
                mma16h(s[2 * p],     qa[c], kb[0], kb[2]);
                mma16h(s[2 * p + 1], qa[c], kb[1], kb[3]);
            }
        }

        // exp + row sums
        float rs0 = 0.f, rs1 = 0.f;
#pragma unroll
        for (int nt = 0; nt < 8; ++nt) {
            float p0 = ex2f_(s[nt][0]), p1 = ex2f_(s[nt][1]);
            float p2 = ex2f_(s[nt][2]), p3 = ex2f_(s[nt][3]);
            s[nt][0] = p0; s[nt][1] = p1; s[nt][2] = p2; s[nt][3] = p3;
            rs0 += p0 + p1; rs1 += p2 + p3;
        }
        rs0 += __shfl_xor_sync(0xffffffffu, rs0, 1);
        rs0 += __shfl_xor_sync(0xffffffffu, rs0, 2);
        rs1 += __shfl_xor_sync(0xffffffffu, rs1, 1);
        rs1 += __shfl_xor_sync(0xffffffffu, rs1, 2);
        l0 += rs0; l1 += rs1;

        // O += P @ V : P fp16 A-frags direct from S regs (no shfl)
#pragma unroll
        for (int t = 0; t < 4; ++t) {
            unsigned pa[4];
            pa[0] = packh(s[2 * t][0],     s[2 * t][1]);
            pa[1] = packh(s[2 * t][2],     s[2 * t][3]);
            pa[2] = packh(s[2 * t + 1][0], s[2 * t + 1][1]);
            pa[3] = packh(s[2 * t + 1][2], s[2 * t + 1][3]);
#pragma unroll
            for (int dp = 0; dp < 4; ++dp) {
                const int j = lane >> 3, rr = lane & 7;
                int key = t * 16 + ((j & 1) << 3) + rr;
                int dcol = dp * 16 + ((j >> 1) << 3);
                unsigned vb[4];
                ldsm4t(vb, vbase + (unsigned)(key * 144 + dcol * 2));
                mma16h(o[2 * dp],     pa, vb[0], vb[1]);
                mma16h(o[2 * dp + 1], pa, vb[2], vb[3]);
            }
        }
    }

    const float inv0 = 1.f / l0, inv1 = 1.f / l1;
    const int bi = bh >> 4, h = bh & 15;
    const int n = q0 + warp * 16 + g;
#pragma unroll
    for (int dt = 0; dt < 8; ++dt) {
        int col = h * 64 + dt * 8 + 2 * tg;
        *(float2*)&g_AO[((size_t)bi * N_ + n) * E_ + col] =
            make_float2(o[dt][0] * inv0, o[dt][1] * inv0);
        *(float2*)&g_AO[((size_t)bi * N_ + n + 8) * E_ + col] =
            make_float2(o[dt][2] * inv1, o[dt][3] * inv1);
    }
}

// ---------------------------------------------------------------------------
extern "C" void kernel_launch(void* const* d_in, const int* in_sizes, int n_in,
                              void* d_out, int out_size)
{
    const float* x   = (const float*)d_in[0];
    const float* ctx = (const float*)d_in[1];
    const float* Wq  = (const float*)d_in[2];
    const float* Wk  = (const float*)d_in[3];
    const float* Wv  = (const float*)d_in[4];
    const float* Wo  = (const float*)d_in[5];
    const float* bo  = (const float*)d_in[6];
    float* out = (float*)d_out;

    float *Qp, *Kp, *Vp, *AOp;
    cudaGetSymbolAddress((void**)&Qp,  g_Q);
    cudaGetSymbolAddress((void**)&Kp,  g_K);
    cudaGetSymbolAddress((void**)&Vp,  g_V);
    cudaGetSymbolAddress((void**)&AOp, g_AO);

    dim3 ggrid(E_ / 128, (B_ * N_) / 128);

    gemm_tc<<<ggrid, 256>>>(x,   Wq, Qp,  nullptr, 0);
    gemm_tc<<<ggrid, 256>>>(ctx, Wk, Kp,  nullptr, 0);
    gemm_tc<<<ggrid, 256>>>(ctx, Wv, Vp,  nullptr, 0);
    attn_tc<<<dim3(N_ / 128, B_ * H_), 256>>>();
    gemm_tc<<<ggrid, 256>>>(AOp, Wo, out, bo, 1);
}

// round 7
// speedup vs baseline: 1.0112x; 1.0112x over previous
#include <cuda_runtime.h>
#include <cuda_bf16.h>
#include <cuda_fp16.h>

#define B_  4
#define N_  2048
#define M_  2048
#define H_  16
#define D_  64
#define E_  1024
#define R_  8192   // B_*N_

// fp16 tensors (projection outputs)
__device__ __half g_Q[(size_t)B_ * H_ * N_ * D_];   // pre-scaled by scale*log2e
__device__ __half g_K[(size_t)B_ * H_ * M_ * D_];
__device__ __half g_V[(size_t)B_ * H_ * M_ * D_];
// split-bf16 operands
__device__ __nv_bfloat16 g_Xhi[(size_t)R_ * E_], g_Xlo[(size_t)R_ * E_];
__device__ __nv_bfloat16 g_Chi[(size_t)R_ * E_], g_Clo[(size_t)R_ * E_];
__device__ __nv_bfloat16 g_AOhi[(size_t)R_ * E_], g_AOlo[(size_t)R_ * E_];
__device__ __nv_bfloat16 g_Wh[(size_t)4 * E_ * E_], g_Wl[(size_t)4 * E_ * E_];

// ---------------------------------------------------------------------------
// helpers
// ---------------------------------------------------------------------------
__device__ __forceinline__ float ex2f_(float x) {
    float y; asm("ex2.approx.f32 %0, %1;" : "=f"(y) : "f"(x)); return y;
}
__device__ __forceinline__ void mma16(float* d, const unsigned* a, unsigned b0, unsigned b1) {
    asm("mma.sync.aligned.m16n8k16.row.col.f32.bf16.bf16.f32 "
        "{%0,%1,%2,%3},{%4,%5,%6,%7},{%8,%9},{%0,%1,%2,%3};"
        : "+f"(d[0]), "+f"(d[1]), "+f"(d[2]), "+f"(d[3])
        : "r"(a[0]), "r"(a[1]), "r"(a[2]), "r"(a[3]), "r"(b0), "r"(b1));
}
__device__ __forceinline__ void mma16h(float* d, const unsigned* a, unsigned b0, unsigned b1) {
    asm("mma.sync.aligned.m16n8k16.row.col.f32.f16.f16.f32 "
        "{%0,%1,%2,%3},{%4,%5,%6,%7},{%8,%9},{%0,%1,%2,%3};"
        : "+f"(d[0]), "+f"(d[1]), "+f"(d[2]), "+f"(d[3])
        : "r"(a[0]), "r"(a[1]), "r"(a[2]), "r"(a[3]), "r"(b0), "r"(b1));
}
__device__ __forceinline__ unsigned packh(float lo, float hi) {
    unsigned r; asm("cvt.rn.f16x2.f32 %0, %1, %2;" : "=r"(r) : "f"(hi), "f"(lo)); return r;
}
__device__ __forceinline__ void ldsm4(unsigned* r, unsigned addr) {
    asm volatile("ldmatrix.sync.aligned.m8n8.x4.shared.b16 {%0,%1,%2,%3}, [%4];"
                 : "=r"(r[0]), "=r"(r[1]), "=r"(r[2]), "=r"(r[3]) : "r"(addr));
}
__device__ __forceinline__ void ldsm4t(unsigned* r, unsigned addr) {
    asm volatile("ldmatrix.sync.aligned.m8n8.x4.trans.shared.b16 {%0,%1,%2,%3}, [%4];"
                 : "=r"(r[0]), "=r"(r[1]), "=r"(r[2]), "=r"(r[3]) : "r"(addr));
}
__device__ __forceinline__ void cpa16(unsigned dst, const void* src) {
    asm volatile("cp.async.cg.shared.global [%0], [%1], 16;" :: "r"(dst), "l"(src));
}
__device__ __forceinline__ void cpacommit() { asm volatile("cp.async.commit_group;"); }
__device__ __forceinline__ void cpawait0()  { asm volatile("cp.async.wait_group 0;"); }

// ---------------------------------------------------------------------------
// Prep: split fp32 -> (hi, lo) bf16 arrays
// ---------------------------------------------------------------------------
__global__ __launch_bounds__(256) void split_k(
    const float* __restrict__ src, __nv_bfloat16* __restrict__ hi,
    __nv_bfloat16* __restrict__ lo, int n4)
{
    int i = blockIdx.x * 256 + threadIdx.x;
    if (i >= n4) return;
    float4 v = ((const float4*)src)[i];
    __nv_bfloat162 h01 = __floats2bfloat162_rn(v.x, v.y);
    __nv_bfloat162 h23 = __floats2bfloat162_rn(v.z, v.w);
    float r0 = v.x - __bfloat162float(h01.x);
    float r1 = v.y - __bfloat162float(h01.y);
    float r2 = v.z - __bfloat162float(h23.x);
    float r3 = v.w - __bfloat162float(h23.y);
    __nv_bfloat162 l01 = __floats2bfloat162_rn(r0, r1);
    __nv_bfloat162 l23 = __floats2bfloat162_rn(r2, r3);
    uint2 hu, lu;
    hu.x = *(unsigned*)&h01; hu.y = *(unsigned*)&h23;
    lu.x = *(unsigned*)&l01; lu.y = *(unsigned*)&l23;
    *(uint2*)&hi[(size_t)i * 4] = hu;
    *(uint2*)&lo[(size_t)i * 4] = lu;
}

// ---------------------------------------------------------------------------
// Split-bf16 GEMM: Y = A (R x 1024) @ Wt^T. Operands PRE-SPLIT in gmem as
// bf16 hi/lo; staging via cp.async (no cvt in mainloop), double-buffered.
// mode 1: fp32 [r][o] + bias; mode 2: fp16 head-split * oscale.
// ---------------------------------------------------------------------------
__global__ __launch_bounds__(256) void gemm_tc(
    const __nv_bfloat16* __restrict__ Ah8, const __nv_bfloat16* __restrict__ Al8,
    const __nv_bfloat16* __restrict__ Bh8, const __nv_bfloat16* __restrict__ Bl8,
    float* __restrict__ Yf, __half* __restrict__ Yh,
    const float* __restrict__ bias, int mode, float oscale)
{
    __shared__ unsigned Ahi[2][1536], Alo[2][1536];   // 128 rows * 12 pairs
    __shared__ unsigned Bhi[2][1536], Blo[2][1536];

    const int tid = threadIdx.x, lane = tid & 31, warp = tid >> 5;
    const int g = lane >> 2, tg = lane & 3;
    const int wm = (warp >> 2) * 64, wn = (warp & 3) * 32;
    const int m0 = blockIdx.y * 128, n0 = blockIdx.x * 128;

    const unsigned ahiB = (unsigned)__cvta_generic_to_shared(Ahi);
    const unsigned aloB = (unsigned)__cvta_generic_to_shared(Alo);
    const unsigned bhiB = (unsigned)__cvta_generic_to_shared(Bhi);
    const unsigned bloB = (unsigned)__cvta_generic_to_shared(Blo);

    const int lrow = ((lane >> 3) & 1) * 8 + (lane & 7);
    const int lkh  = lane >> 4;
    const unsigned aoff = (unsigned)((wm + lrow) * 48 + lkh * 16);
    const unsigned boff = (unsigned)((wn + lrow) * 48 + lkh * 16);

    const int crow = tid >> 1, chalf = tid & 1;
    const size_t aso = (size_t)(m0 + crow) * E_ + chalf * 8;
    const size_t bso = (size_t)(n0 + crow) * E_ + chalf * 8;
    const unsigned cdst = (unsigned)(crow * 48 + chalf * 16);

    auto issue = [&](int c, int b) {
        const unsigned d = cdst + (unsigned)b * 6144u;
        const int k16 = c * 16;
        cpa16(ahiB + d, Ah8 + aso + k16);
        cpa16(aloB + d, Al8 + aso + k16);
        cpa16(bhiB + d, Bh8 + bso + k16);
        cpa16(bloB + d, Bl8 + bso + k16);
        cpacommit();
    };

    float acc[4][4][4];
#pragma unroll
    for (int i = 0; i < 4; ++i)
#pragma unroll
        for (int j = 0; j < 4; ++j)
#pragma unroll
            for (int k = 0; k < 4; ++k) acc[i][j][k] = 0.f;

    issue(0, 0);
    for (int c = 0; c < 64; ++c) {
        cpawait0();
        __syncthreads();
        if (c < 63) issue(c + 1, (c + 1) & 1);
        const unsigned bufo = (unsigned)(c & 1) * 6144u;

        unsigned ah[4][4], al[4][4], bh[2][4], bl[2][4];
#pragma unroll
        for (int mt = 0; mt < 4; ++mt) {
            unsigned o_ = bufo + aoff + (unsigned)mt * 768u;
            ldsm4(ah[mt], ahiB + o_);
            ldsm4(al[mt], aloB + o_);
        }
#pragma unroll
        for (int p = 0; p < 2; ++p) {
            unsigned o_ = bufo + boff + (unsigned)p * 768u;
            ldsm4(bh[p], bhiB + o_);
            ldsm4(bl[p], bloB + o_);
        }
#pragma unroll
        for (int mt = 0; mt < 4; ++mt)
#pragma unroll
            for (int nt = 0; nt < 4; ++nt) {
                const int p = nt >> 1, sel = nt & 1;
                mma16(acc[mt][nt], ah[mt], bh[p][sel], bh[p][sel + 2]);
                mma16(acc[mt][nt], ah[mt], bl[p][sel], bl[p][sel + 2]);
                mma16(acc[mt][nt], al[mt], bh[p][sel], bh[p][sel + 2]);
            }
    }

    if (mode == 2) {
#pragma unroll
        for (int mt = 0; mt < 4; ++mt) {
            int m = m0 + wm + mt * 16 + g;
            int bi = m >> 11, n = m & 2047;
#pragma unroll
            for (int nt = 0; nt < 4; ++nt) {
                int o = n0 + wn + nt * 8 + 2 * tg;
                int h = o >> 6, d = o & 63;
                __half2 u0 = __floats2half2_rn(acc[mt][nt][0] * oscale, acc[mt][nt][1] * oscale);
                __half2 u1 = __floats2half2_rn(acc[mt][nt][2] * oscale, acc[mt][nt][3] * oscale);
                *(unsigned*)&Yh[(((size_t)(bi * H_ + h)) * 2048 + n) * D_ + d] = *(unsigned*)&u0;
                *(unsigned*)&Yh[(((size_t)(bi * H_ + h)) * 2048 + n + 8) * D_ + d] = *(unsigned*)&u1;
            }
        }
    } else {
#pragma unroll
        for (int mt = 0; mt < 4; ++mt) {
            int m = m0 + wm + mt * 16 + g;
#pragma unroll
            for (int nt = 0; nt < 4; ++nt) {
                int o = n0 + wn + nt * 8 + 2 * tg;
                float bx = bias[o], by = bias[o + 1];
                *(float2*)&Yf[(size_t)m * E_ + o] =
                    make_float2(acc[mt][nt][0] + bx, acc[mt][nt][1] + by);
                *(float2*)&Yf[(size_t)(m + 8) * E_ + o] =
                    make_float2(acc[mt][nt][2] + bx, acc[mt][nt][3] + by);
            }
        }
    }
}

// ---------------------------------------------------------------------------
// Attention: all fp16 MMAs. K/V already fp16 in gmem -> cp.async staging
// (double-buffered); Q already fp16 pre-scaled -> direct u32 fragment loads.
// P A-frags direct from S regs (no shfl). Output written pre-split bf16.
// ---------------------------------------------------------------------------
__global__ __launch_bounds__(256, 2) void attn_tc()
{
    __shared__ unsigned Ks2[2][64 * 36];   // fp16 pairs, row stride 144B
    __shared__ unsigned Vs2[2][64 * 36];

    const int tid = threadIdx.x, lane = tid & 31, warp = tid >> 5;
    const int g = lane >> 2, tg = lane & 3;
    const int bh = blockIdx.y, q0 = blockIdx.x * 128;

    // Q A-fragments: direct u32 loads (pre-scaled fp16 pairs)
    const unsigned* Qg = (const unsigned*)(g_Q + ((size_t)bh * N_ + q0 + warp * 16) * D_);
    unsigned qa[4][4];
#pragma unroll
    for (int c = 0; c < 4; ++c) {
        qa[c][0] = Qg[g * 32 + c * 8 + tg];
        qa[c][1] = Qg[(g + 8) * 32 + c * 8 + tg];
        qa[c][2] = Qg[g * 32 + c * 8 + tg + 4];
        qa[c][3] = Qg[(g + 8) * 32 + c * 8 + tg + 4];
    }

    float o[8][4];
#pragma unroll
    for (int i = 0; i < 8; ++i)
#pragma unroll
        for (int j = 0; j < 4; ++j) o[i][j] = 0.f;
    float l0 = 0.f, l1 = 0.f;

    const __half* Kh = g_K + (size_t)bh * M_ * D_;
    const __half* Vh = g_V + (size_t)bh * M_ * D_;
    const unsigned kb0 = (unsigned)__cvta_generic_to_shared(Ks2);
    const unsigned vb0 = (unsigned)__cvta_generic_to_shared(Vs2);
    const int lrow = ((lane >> 3) & 1) * 8 + (lane & 7);
    const int lkh  = lane >> 4;

    const int srow = tid >> 2, si = tid & 3;
    auto issue = [&](int t, int b) {
        const __half* kr = Kh + (size_t)(t * 64 + srow) * D_;
        const __half* vr = Vh + (size_t)(t * 64 + srow) * D_;
        unsigned kd = kb0 + (unsigned)b * 9216u + (unsigned)(srow * 144 + si * 16);
        unsigned vd = vb0 + (unsigned)b * 9216u + (unsigned)(srow * 144 + si * 16);
        cpa16(kd,      kr + si * 8);
        cpa16(kd + 64, kr + si * 8 + 32);
        cpa16(vd,      vr + si * 8);
        cpa16(vd + 64, vr + si * 8 + 32);
        cpacommit();
    };

    issue(0, 0);
    for (int t = 0; t < 32; ++t) {
        cpawait0();
        __syncthreads();
        if (t < 31) issue(t + 1, (t + 1) & 1);
        const unsigned bufo = (unsigned)(t & 1) * 9216u;

        // S = Q K^T (fp16 MMA, fp32 accum); scale already folded into Q
        float s[8][4];
#pragma unroll
        for (int nt = 0; nt < 8; ++nt)
#pragma unroll
            for (int j = 0; j < 4; ++j) s[nt][j] = 0.f;
#pragma unroll
        for (int c = 0; c < 4; ++c) {
#pragma unroll
            for (int p = 0; p < 4; ++p) {
                unsigned kb[4];
                ldsm4(kb, kb0 + bufo + (unsigned)((p * 16 + lrow) * 144 + c * 32 + lkh * 16));
                mma16h(s[2 * p],     qa[c], kb[0], kb[2]);
                mma16h(s[2 * p + 1], qa[c], kb[1], kb[3]);
            }
        }

        // exp + row sums
        float rs0 = 0.f, rs1 = 0.f;
#pragma unroll
        for (int nt = 0; nt < 8; ++nt) {
            float p0 = ex2f_(s[nt][0]), p1 = ex2f_(s[nt][1]);
            float p2 = ex2f_(s[nt][2]), p3 = ex2f_(s[nt][3]);
            s[nt][0] = p0; s[nt][1] = p1; s[nt][2] = p2; s[nt][3] = p3;
            rs0 += p0 + p1; rs1 += p2 + p3;
        }
        rs0 += __shfl_xor_sync(0xffffffffu, rs0, 1);
        rs0 += __shfl_xor_sync(0xffffffffu, rs0, 2);
        rs1 += __shfl_xor_sync(0xffffffffu, rs1, 1);
        rs1 += __shfl_xor_sync(0xffffffffu, rs1, 2);
        l0 += rs0; l1 += rs1;

        // O += P @ V
#pragma unroll
        for (int tt = 0; tt < 4; ++tt) {
            unsigned pa[4];
            pa[0] = packh(s[2 * tt][0],     s[2 * tt][1]);
            pa[1] = packh(s[2 * tt][2],     s[2 * tt][3]);
            pa[2] = packh(s[2 * tt + 1][0], s[2 * tt + 1][1]);
            pa[3] = packh(s[2 * tt + 1][2], s[2 * tt + 1][3]);
#pragma unroll
            for (int dp = 0; dp < 4; ++dp) {
                const int j = lane >> 3, rr = lane & 7;
                int key = tt * 16 + ((j & 1) << 3) + rr;
                int dcol = dp * 16 + ((j >> 1) << 3);
                unsigned vb[4];
                ldsm4t(vb, vb0 + bufo + (unsigned)(key * 144 + dcol * 2));
                mma16h(o[2 * dp],     pa, vb[0], vb[1]);
                mma16h(o[2 * dp + 1], pa, vb[2], vb[3]);
            }
        }
    }

    // normalize + split-bf16 write to g_AOhi / g_AOlo
    const float inv0 = 1.f / l0, inv1 = 1.f / l1;
    const int bi = bh >> 4, h = bh & 15;
    const int n = q0 + warp * 16 + g;
    auto wsplit = [&](float a, float b, size_t off) {
        __nv_bfloat162 hh = __floats2bfloat162_rn(a, b);
        float ra = a - __bfloat162float(hh.x);
        float rb = b - __bfloat162float(hh.y);
        __nv_bfloat162 ll = __floats2bfloat162_rn(ra, rb);
        *(unsigned*)&g_AOhi[off] = *(unsigned*)&hh;
        *(unsigned*)&g_AOlo[off] = *(unsigned*)&ll;
    };
#pragma unroll
    for (int dt = 0; dt < 8; ++dt) {
        int col = h * 64 + dt * 8 + 2 * tg;
        wsplit(o[dt][0] * inv0, o[dt][1] * inv0, ((size_t)bi * N_ + n) * E_ + col);
        wsplit(o[dt][2] * inv1, o[dt][3] * inv1, ((size_t)bi * N_ + n + 8) * E_ + col);
    }
}

// ---------------------------------------------------------------------------
extern "C" void kernel_launch(void* const* d_in, const int* in_sizes, int n_in,
                              void* d_out, int out_size)
{
    const float* x   = (const float*)d_in[0];
    const float* ctx = (const float*)d_in[1];
    const float* Wq  = (const float*)d_in[2];
    const float* Wk  = (const float*)d_in[3];
    const float* Wv  = (const float*)d_in[4];
    const float* Wo  = (const float*)d_in[5];
    const float* bo  = (const float*)d_in[6];
    float* out = (float*)d_out;

    __half *Qp, *Kp, *Vp;
    __nv_bfloat16 *Xh, *Xl, *Ch, *Cl, *Ah, *Al, *Wh, *Wl;
    cudaGetSymbolAddress((void**)&Qp, g_Q);
    cudaGetSymbolAddress((void**)&Kp, g_K);
    cudaGetSymbolAddress((void**)&Vp, g_V);
    cudaGetSymbolAddress((void**)&Xh, g_Xhi);
    cudaGetSymbolAddress((void**)&Xl, g_Xlo);
    cudaGetSymbolAddress((void**)&Ch, g_Chi);
    cudaGetSymbolAddress((void**)&Cl, g_Clo);
    cudaGetSymbolAddress((void**)&Ah, g_AOhi);
    cudaGetSymbolAddress((void**)&Al, g_AOlo);
    cudaGetSymbolAddress((void**)&Wh, g_Wh);
    cudaGetSymbolAddress((void**)&Wl, g_Wl);

    const int n4x = R_ * E_ / 4;       // 2M
    const int n4w = E_ * E_ / 4;       // 256K
    const size_t WSZ = (size_t)E_ * E_;
    split_k<<<n4x / 256, 256>>>(x,   Xh, Xl, n4x);
    split_k<<<n4x / 256, 256>>>(ctx, Ch, Cl, n4x);
    split_k<<<n4w / 256, 256>>>(Wq, Wh + 0 * WSZ, Wl + 0 * WSZ, n4w);
    split_k<<<n4w / 256, 256>>>(Wk, Wh + 1 * WSZ, Wl + 1 * WSZ, n4w);
    split_k<<<n4w / 256, 256>>>(Wv, Wh + 2 * WSZ, Wl + 2 * WSZ, n4w);
    split_k<<<n4w / 256, 256>>>(Wo, Wh + 3 * WSZ, Wl + 3 * WSZ, n4w);

    dim3 ggrid(E_ / 128, R_ / 128);    // (8, 64)
    const float qs = 0.125f * 1.4426950408889634f;

    gemm_tc<<<ggrid, 256>>>(Xh, Xl, Wh + 0 * WSZ, Wl + 0 * WSZ, nullptr, Qp, nullptr, 2, qs);
    gemm_tc<<<ggrid, 256>>>(Ch, Cl, Wh + 1 * WSZ, Wl + 1 * WSZ, nullptr, Kp, nullptr, 2, 1.f);
    gemm_tc<<<ggrid, 256>>>(Ch, Cl, Wh + 2 * WSZ, Wl + 2 * WSZ, nullptr, Vp, nullptr, 2, 1.f);
    attn_tc<<<dim3(N_ / 128, B_ * H_), 256>>>();
    gemm_tc<<<ggrid, 256>>>(Ah, Al, Wh + 3 * WSZ, Wl + 3 * WSZ, out, nullptr, bo, 1, 1.f);
}

// round 8
// speedup vs baseline: 1.9146x; 1.8933x over previous
#include <cuda_runtime.h>
#include <cuda_fp16.h>

#define B_  4
#define N_  2048
#define M_  2048
#define H_  16
#define D_  64
#define E_  1024
#define R_  8192   // B_*N_

// fp16 tensors
__device__ __half g_Q[(size_t)B_ * H_ * N_ * D_];   // pre-scaled by scale*log2e (folded into Wq)
__device__ __half g_K[(size_t)B_ * H_ * M_ * D_];
__device__ __half g_V[(size_t)B_ * H_ * M_ * D_];
__device__ __half g_Xh[(size_t)R_ * E_];
__device__ __half g_Ch[(size_t)R_ * E_];
__device__ __half g_AO[(size_t)R_ * E_];
__device__ __half g_W4[(size_t)4 * E_ * E_];

// ---------------------------------------------------------------------------
// helpers
// ---------------------------------------------------------------------------
__device__ __forceinline__ float ex2f_(float x) {
    float y; asm("ex2.approx.f32 %0, %1;" : "=f"(y) : "f"(x)); return y;
}
__device__ __forceinline__ void mma16h(float* d, const unsigned* a, unsigned b0, unsigned b1) {
    asm("mma.sync.aligned.m16n8k16.row.col.f32.f16.f16.f32 "
        "{%0,%1,%2,%3},{%4,%5,%6,%7},{%8,%9},{%0,%1,%2,%3};"
        : "+f"(d[0]), "+f"(d[1]), "+f"(d[2]), "+f"(d[3])
        : "r"(a[0]), "r"(a[1]), "r"(a[2]), "r"(a[3]), "r"(b0), "r"(b1));
}
__device__ __forceinline__ unsigned packh(float lo, float hi) {
    unsigned r; asm("cvt.rn.f16x2.f32 %0, %1, %2;" : "=r"(r) : "f"(hi), "f"(lo)); return r;
}
__device__ __forceinline__ void ldsm4(unsigned* r, unsigned addr) {
    asm volatile("ldmatrix.sync.aligned.m8n8.x4.shared.b16 {%0,%1,%2,%3}, [%4];"
                 : "=r"(r[0]), "=r"(r[1]), "=r"(r[2]), "=r"(r[3]) : "r"(addr));
}
__device__ __forceinline__ void ldsm4t(unsigned* r, unsigned addr) {
    asm volatile("ldmatrix.sync.aligned.m8n8.x4.trans.shared.b16 {%0,%1,%2,%3}, [%4];"
                 : "=r"(r[0]), "=r"(r[1]), "=r"(r[2]), "=r"(r[3]) : "r"(addr));
}
__device__ __forceinline__ void cpa16(unsigned dst, const void* src) {
    asm volatile("cp.async.cg.shared.global [%0], [%1], 16;" :: "r"(dst), "l"(src));
}
__device__ __forceinline__ void cpacommit() { asm volatile("cp.async.commit_group;"); }
__device__ __forceinline__ void cpawait0()  { asm volatile("cp.async.wait_group 0;"); }
__device__ __forceinline__ void cpawait1()  { asm volatile("cp.async.wait_group 1;"); }

// ---------------------------------------------------------------------------
// Prep: fp32 -> fp16 convert (optionally scaled)
// ---------------------------------------------------------------------------
__global__ __launch_bounds__(256) void f2h(
    const float* __restrict__ src, __half* __restrict__ dst, int n4, float scale)
{
    int i = blockIdx.x * 256 + threadIdx.x;
    if (i >= n4) return;
    float4 v = ((const float4*)src)[i];
    __half2 a = __floats2half2_rn(v.x * scale, v.y * scale);
    __half2 b = __floats2half2_rn(v.z * scale, v.w * scale);
    uint2 u; u.x = *(unsigned*)&a; u.y = *(unsigned*)&b;
    *(uint2*)&dst[(size_t)i * 4] = u;
}

// ---------------------------------------------------------------------------
// Single-fp16 GEMM: Y = A (R x 1024) @ W^T, fp32 accumulate.
// Block 128x128, 8 warps (2x4), warp tile 64x32, K-chunks of 16.
// smem rows: 16 halfs at 48B stride (conflict-free ldmatrix); 3-stage cp.async.
// mode 1: fp32 [r][o] + bias; mode 2: fp16 head-split.
// ---------------------------------------------------------------------------
__global__ __launch_bounds__(256) void gemm_h(
    const __half* __restrict__ A, const __half* __restrict__ Bw,
    float* __restrict__ Yf, __half* __restrict__ Yh,
    const float* __restrict__ bias, int mode)
{
    __shared__ unsigned As[3][1536], Bs[3][1536];   // 128 rows * 12 u32 (48B)

    const int tid = threadIdx.x, lane = tid & 31, warp = tid >> 5;
    const int g = lane >> 2, tg = lane & 3;
    const int wm = (warp >> 2) * 64, wn = (warp & 3) * 32;
    const int m0 = blockIdx.y * 128, n0 = blockIdx.x * 128;

    const unsigned asB = (unsigned)__cvta_generic_to_shared(As);
    const unsigned bsB = (unsigned)__cvta_generic_to_shared(Bs);
    const int lrow = ((lane >> 3) & 1) * 8 + (lane & 7);
    const int lkh  = lane >> 4;
    const unsigned aoff = (unsigned)((wm + lrow) * 48 + lkh * 16);
    const unsigned boff = (unsigned)((wn + lrow) * 48 + lkh * 16);

    const int crow = tid >> 1, chalf = tid & 1;
    const __half* Asrc = A  + (size_t)(m0 + crow) * E_ + chalf * 8;
    const __half* Bsrc = Bw + (size_t)(n0 + crow) * E_ + chalf * 8;
    const unsigned cdst = (unsigned)(crow * 48 + chalf * 16);

    auto issue = [&](int c) {
        const unsigned d = cdst + (unsigned)(c % 3) * 6144u;
        cpa16(asB + d, Asrc + c * 16);
        cpa16(bsB + d, Bsrc + c * 16);
        cpacommit();
    };

    float acc[4][4][4];
#pragma unroll
    for (int i = 0; i < 4; ++i)
#pragma unroll
        for (int j = 0; j < 4; ++j)
#pragma unroll
            for (int k = 0; k < 4; ++k) acc[i][j][k] = 0.f;

    issue(0);
    issue(1);
    for (int c = 0; c < 64; ++c) {
        if (c < 63) cpawait1(); else cpawait0();
        __syncthreads();
        if (c < 62) issue(c + 2);
        const unsigned bufo = (unsigned)(c % 3) * 6144u;

        unsigned ah[4][4], bh[2][4];
#pragma unroll
        for (int mt = 0; mt < 4; ++mt)
            ldsm4(ah[mt], asB + bufo + aoff + (unsigned)mt * 768u);
#pragma unroll
        for (int p = 0; p < 2; ++p)
            ldsm4(bh[p], bsB + bufo + boff + (unsigned)p * 768u);
#pragma unroll
        for (int mt = 0; mt < 4; ++mt)
#pragma unroll
            for (int nt = 0; nt < 4; ++nt) {
                const int p = nt >> 1, sel = nt & 1;
                mma16h(acc[mt][nt], ah[mt], bh[p][sel], bh[p][sel + 2]);
            }
    }

    if (mode == 2) {
#pragma unroll
        for (int mt = 0; mt < 4; ++mt) {
            int m = m0 + wm + mt * 16 + g;
            int bi = m >> 11, n = m & 2047;
#pragma unroll
            for (int nt = 0; nt < 4; ++nt) {
                int o = n0 + wn + nt * 8 + 2 * tg;
                int h = o >> 6, d = o & 63;
                __half2 u0 = __floats2half2_rn(acc[mt][nt][0], acc[mt][nt][1]);
                __half2 u1 = __floats2half2_rn(acc[mt][nt][2], acc[mt][nt][3]);
                *(unsigned*)&Yh[(((size_t)(bi * H_ + h)) * 2048 + n) * D_ + d] = *(unsigned*)&u0;
                *(unsigned*)&Yh[(((size_t)(bi * H_ + h)) * 2048 + n + 8) * D_ + d] = *(unsigned*)&u1;
            }
        }
    } else {
#pragma unroll
        for (int mt = 0; mt < 4; ++mt) {
            int m = m0 + wm + mt * 16 + g;
#pragma unroll
            for (int nt = 0; nt < 4; ++nt) {
                int o = n0 + wn + nt * 8 + 2 * tg;
                float bx = bias[o], by = bias[o + 1];
                *(float2*)&Yf[(size_t)m * E_ + o] =
                    make_float2(acc[mt][nt][0] + bx, acc[mt][nt][1] + by);
                *(float2*)&Yf[(size_t)(m + 8) * E_ + o] =
                    make_float2(acc[mt][nt][2] + bx, acc[mt][nt][3] + by);
            }
        }
    }
}

// ---------------------------------------------------------------------------
// Attention: all fp16 MMAs, fp32 accum/softmax. K/V staged via cp.async
// (double-buffered). Q fragments direct u32 loads (pre-scaled). P A-frags
// direct from S registers (no shfl). Output fp16.
// ---------------------------------------------------------------------------
__global__ __launch_bounds__(256, 2) void attn_tc()
{
    __shared__ unsigned Ks2[2][64 * 36];   // fp16 pairs, row stride 144B
    __shared__ unsigned Vs2[2][64 * 36];

    const int tid = threadIdx.x, lane = tid & 31, warp = tid >> 5;
    const int g = lane >> 2, tg = lane & 3;
    const int bh = blockIdx.y, q0 = blockIdx.x * 128;

    const unsigned* Qg = (const unsigned*)(g_Q + ((size_t)bh * N_ + q0 + warp * 16) * D_);
    unsigned qa[4][4];
#pragma unroll
    for (int c = 0; c < 4; ++c) {
        qa[c][0] = Qg[g * 32 + c * 8 + tg];
        qa[c][1] = Qg[(g + 8) * 32 + c * 8 + tg];
        qa[c][2] = Qg[g * 32 + c * 8 + tg + 4];
        qa[c][3] = Qg[(g + 8) * 32 + c * 8 + tg + 4];
    }

    float o[8][4];
#pragma unroll
    for (int i = 0; i < 8; ++i)
#pragma unroll
        for (int j = 0; j < 4; ++j) o[i][j] = 0.f;
    float l0 = 0.f, l1 = 0.f;

    const __half* Kh = g_K + (size_t)bh * M_ * D_;
    const __half* Vh = g_V + (size_t)bh * M_ * D_;
    const unsigned kb0 = (unsigned)__cvta_generic_to_shared(Ks2);
    const unsigned vb0 = (unsigned)__cvta_generic_to_shared(Vs2);
    const int lrow = ((lane >> 3) & 1) * 8 + (lane & 7);
    const int lkh  = lane >> 4;

    const int srow = tid >> 2, si = tid & 3;
    auto issue = [&](int t, int b) {
        const __half* kr = Kh + (size_t)(t * 64 + srow) * D_;
        const __half* vr = Vh + (size_t)(t * 64 + srow) * D_;
        unsigned kd = kb0 + (unsigned)b * 9216u + (unsigned)(srow * 144 + si * 16);
        unsigned vd = vb0 + (unsigned)b * 9216u + (unsigned)(srow * 144 + si * 16);
        cpa16(kd,      kr + si * 8);
        cpa16(kd + 64, kr + si * 8 + 32);
        cpa16(vd,      vr + si * 8);
        cpa16(vd + 64, vr + si * 8 + 32);
        cpacommit();
    };

    issue(0, 0);
    for (int t = 0; t < 32; ++t) {
        cpawait0();
        __syncthreads();
        if (t < 31) issue(t + 1, (t + 1) & 1);
        const unsigned bufo = (unsigned)(t & 1) * 9216u;

        float s[8][4];
#pragma unroll
        for (int nt = 0; nt < 8; ++nt)
#pragma unroll
            for (int j = 0; j < 4; ++j) s[nt][j] = 0.f;
#pragma unroll
        for (int c = 0; c < 4; ++c) {
#pragma unroll
            for (int p = 0; p < 4; ++p) {
                unsigned kb[4];
                ldsm4(kb, kb0 + bufo + (unsigned)((p * 16 + lrow) * 144 + c * 32 + lkh * 16));
                mma16h(s[2 * p],     qa[c], kb[0], kb[2]);
                mma16h(s[2 * p + 1], qa[c], kb[1], kb[3]);
            }
        }

        float rs0 = 0.f, rs1 = 0.f;
#pragma unroll
        for (int nt = 0; nt < 8; ++nt) {
            float p0 = ex2f_(s[nt][0]), p1 = ex2f_(s[nt][1]);
            float p2 = ex2f_(s[nt][2]), p3 = ex2f_(s[nt][3]);
            s[nt][0] = p0; s[nt][1] = p1; s[nt][2] = p2; s[nt][3] = p3;
            rs0 += p0 + p1; rs1 += p2 + p3;
        }
        rs0 += __shfl_xor_sync(0xffffffffu, rs0, 1);
        rs0 += __shfl_xor_sync(0xffffffffu, rs0, 2);
        rs1 += __shfl_xor_sync(0xffffffffu, rs1, 1);
        rs1 += __shfl_xor_sync(0xffffffffu, rs1, 2);
        l0 += rs0; l1 += rs1;

#pragma unroll
        for (int tt = 0; tt < 4; ++tt) {
            unsigned pa[4];
            pa[0] = packh(s[2 * tt][0],     s[2 * tt][1]);
            pa[1] = packh(s[2 * tt][2],     s[2 * tt][3]);
            pa[2] = packh(s[2 * tt + 1][0], s[2 * tt + 1][1]);
            pa[3] = packh(s[2 * tt + 1][2], s[2 * tt + 1][3]);
#pragma unroll
            for (int dp = 0; dp < 4; ++dp) {
                const int j = lane >> 3, rr = lane & 7;
                int key = tt * 16 + ((j & 1) << 3) + rr;
                int dcol = dp * 16 + ((j >> 1) << 3);
                unsigned vb[4];
                ldsm4t(vb, vb0 + bufo + (unsigned)(key * 144 + dcol * 2));
                mma16h(o[2 * dp],     pa, vb[0], vb[1]);
                mma16h(o[2 * dp + 1], pa, vb[2], vb[3]);
            }
        }
    }

    const float inv0 = 1.f / l0, inv1 = 1.f / l1;
    const int bi = bh >> 4, h = bh & 15;
    const int n = q0 + warp * 16 + g;
#pragma unroll
    for (int dt = 0; dt < 8; ++dt) {
        int col = h * 64 + dt * 8 + 2 * tg;
        __half2 u0 = __floats2half2_rn(o[dt][0] * inv0, o[dt][1] * inv0);
        __half2 u1 = __floats2half2_rn(o[dt][2] * inv1, o[dt][3] * inv1);
        *(unsigned*)&g_AO[((size_t)bi * N_ + n) * E_ + col] = *(unsigned*)&u0;
        *(unsigned*)&g_AO[((size_t)bi * N_ + n + 8) * E_ + col] = *(unsigned*)&u1;
    }
}

// ---------------------------------------------------------------------------
extern "C" void kernel_launch(void* const* d_in, const int* in_sizes, int n_in,
                              void* d_out, int out_size)
{
    const float* x   = (const float*)d_in[0];
    const float* ctx = (const float*)d_in[1];
    const float* Wq  = (const float*)d_in[2];
    const float* Wk  = (const float*)d_in[3];
    const float* Wv  = (const float*)d_in[4];
    const float* Wo  = (const float*)d_in[5];
    const float* bo  = (const float*)d_in[6];
    float* out = (float*)d_out;

    __half *Qp, *Kp, *Vp, *Xh, *Ch, *AOp, *W4;
    cudaGetSymbolAddress((void**)&Qp,  g_Q);
    cudaGetSymbolAddress((void**)&Kp,  g_K);
    cudaGetSymbolAddress((void**)&Vp,  g_V);
    cudaGetSymbolAddress((void**)&Xh,  g_Xh);
    cudaGetSymbolAddress((void**)&Ch,  g_Ch);
    cudaGetSymbolAddress((void**)&AOp, g_AO);
    cudaGetSymbolAddress((void**)&W4,  g_W4);

    const int n4x = R_ * E_ / 4;       // 2M
    const int n4w = E_ * E_ / 4;       // 256K
    const size_t WSZ = (size_t)E_ * E_;
    const float qs = 0.125f * 1.4426950408889634f;   // scale * log2(e), folded into Wq

    f2h<<<n4x / 256, 256>>>(x,   Xh, n4x, 1.f);
    f2h<<<n4x / 256, 256>>>(ctx, Ch, n4x, 1.f);
    f2h<<<n4w / 256, 256>>>(Wq, W4 + 0 * WSZ, n4w, qs);
    f2h<<<n4w / 256, 256>>>(Wk, W4 + 1 * WSZ, n4w, 1.f);
    f2h<<<n4w / 256, 256>>>(Wv, W4 + 2 * WSZ, n4w, 1.f);
    f2h<<<n4w / 256, 256>>>(Wo, W4 + 3 * WSZ, n4w, 1.f);

    dim3 ggrid(E_ / 128, R_ / 128);    // (8, 64)
    gemm_h<<<ggrid, 256>>>(Xh, W4 + 0 * WSZ, nullptr, Qp, nullptr, 2);
    gemm_h<<<ggrid, 256>>>(Ch, W4 + 1 * WSZ, nullptr, Kp, nullptr, 2);
    gemm_h<<<ggrid, 256>>>(Ch, W4 + 2 * WSZ, nullptr, Vp, nullptr, 2);
    attn_tc<<<dim3(N_ / 128, B_ * H_), 256>>>();
    gemm_h<<<ggrid, 256>>>(AOp, W4 + 3 * WSZ, out, nullptr, bo, 1);
}

// round 11
// speedup vs baseline: 1.9925x; 1.0407x over previous
#include <cuda_runtime.h>
#include <cuda_fp16.h>
#include <cstdint>

#define B_  4
#define N_  2048
#define M_  2048
#define H_  16
#define D_  64
#define E_  1024
#define R_  8192   // B_*N_

// fp16 tensors
__device__ __half g_Q[(size_t)B_ * H_ * N_ * D_];   // pre-scaled (scale*log2e folded into Wq)
__device__ __half g_K[(size_t)B_ * H_ * M_ * D_];
__device__ __half g_V[(size_t)B_ * H_ * M_ * D_];
__device__ __half g_Xh[(size_t)R_ * E_];
__device__ __half g_Ch[(size_t)R_ * E_];
__device__ __half g_AO[(size_t)R_ * E_];
__device__ __half g_W4[(size_t)4 * E_ * E_];

// ---------------------------------------------------------------------------
// helpers
// ---------------------------------------------------------------------------
__device__ __forceinline__ void mma16h(float* d, const unsigned* a, unsigned b0, unsigned b1) {
    asm("mma.sync.aligned.m16n8k16.row.col.f32.f16.f16.f32 "
        "{%0,%1,%2,%3},{%4,%5,%6,%7},{%8,%9},{%0,%1,%2,%3};"
        : "+f"(d[0]), "+f"(d[1]), "+f"(d[2]), "+f"(d[3])
        : "r"(a[0]), "r"(a[1]), "r"(a[2]), "r"(a[3]), "r"(b0), "r"(b1));
}
__device__ __forceinline__ unsigned packh(float lo, float hi) {
    unsigned r; asm("cvt.rn.f16x2.f32 %0, %1, %2;" : "=r"(r) : "f"(hi), "f"(lo)); return r;
}
__device__ __forceinline__ unsigned h2ex2(unsigned x) {
    unsigned y; asm("ex2.approx.f16x2 %0, %1;" : "=r"(y) : "r"(x)); return y;
}
__device__ __forceinline__ void ldsm4(unsigned* r, unsigned addr) {
    asm volatile("ldmatrix.sync.aligned.m8n8.x4.shared.b16 {%0,%1,%2,%3}, [%4];"
                 : "=r"(r[0]), "=r"(r[1]), "=r"(r[2]), "=r"(r[3]) : "r"(addr));
}
__device__ __forceinline__ void ldsm4t(unsigned* r, unsigned addr) {
    asm volatile("ldmatrix.sync.aligned.m8n8.x4.trans.shared.b16 {%0,%1,%2,%3}, [%4];"
                 : "=r"(r[0]), "=r"(r[1]), "=r"(r[2]), "=r"(r[3]) : "r"(addr));
}
__device__ __forceinline__ void cpa16(unsigned dst, const void* src) {
    asm volatile("cp.async.cg.shared.global [%0], [%1], 16;" :: "r"(dst), "l"(src));
}
__device__ __forceinline__ void cpacommit() { asm volatile("cp.async.commit_group;"); }
__device__ __forceinline__ void cpawait0()  { asm volatile("cp.async.wait_group 0;"); }
__device__ __forceinline__ void cpawait1()  { asm volatile("cp.async.wait_group 1;"); }
__device__ __forceinline__ void cpawait2()  { asm volatile("cp.async.wait_group 2;"); }
__device__ __forceinline__ unsigned smem_u32(const void* p) {
    unsigned a;
    asm("{ .reg .u64 t; cvta.to.shared.u64 t, %1; cvt.u32.u64 %0, t; }" : "=r"(a) : "l"(p));
    return a;
}
#define ONESH2 0x3C003C00u   // fp16x2 {1.0, 1.0}

// ---------------------------------------------------------------------------
// Prep: fp32 -> fp16 convert
// ---------------------------------------------------------------------------
__global__ __launch_bounds__(256) void f2h(
    const float* __restrict__ src, __half* __restrict__ dst, int n4, float scale)
{
    int i = blockIdx.x * 256 + threadIdx.x;
    if (i >= n4) return;
    float4 v = ((const float4*)src)[i];
    __half2 a = __floats2half2_rn(v.x * scale, v.y * scale);
    __half2 b = __floats2half2_rn(v.z * scale, v.w * scale);
    uint2 u; u.x = *(unsigned*)&a; u.y = *(unsigned*)&b;
    *(uint2*)&dst[(size_t)i * 4] = u;
}
__global__ __launch_bounds__(256) void f2hw(
    const float* __restrict__ w0, const float* __restrict__ w1,
    const float* __restrict__ w2, const float* __restrict__ w3,
    __half* __restrict__ dst, float qs)
{
    int i = blockIdx.x * 256 + threadIdx.x;
    const int per = E_ * E_ / 4;
    int s = i / per, j = i - s * per;
    const float* src = (s == 0) ? w0 : (s == 1) ? w1 : (s == 2) ? w2 : w3;
    float scale = (s == 0) ? qs : 1.f;
    float4 v = ((const float4*)src)[j];
    __half2 a = __floats2half2_rn(v.x * scale, v.y * scale);
    __half2 b = __floats2half2_rn(v.z * scale, v.w * scale);
    uint2 u; u.x = *(unsigned*)&a; u.y = *(unsigned*)&b;
    *(uint2*)&dst[(size_t)i * 4] = u;
}

// ---------------------------------------------------------------------------
// Single-fp16 GEMM (round-8 proven): Y = A (R x 1024) @ W^T, fp32 accumulate.
// Block 128x128, 8 warps, warp tile 64x32, 3-stage cp.async, ldmatrix frags.
// ---------------------------------------------------------------------------
__global__ __launch_bounds__(256) void gemm_h(
    const __half* __restrict__ A, const __half* __restrict__ Bw,
    float* __restrict__ Yf, __half* __restrict__ Yh,
    const float* __restrict__ bias, int mode)
{
    __shared__ unsigned As[3][1536], Bs[3][1536];   // 128 rows * 12 u32 (48B)

    const int tid = threadIdx.x, lane = tid & 31, warp = tid >> 5;
    const int g = lane >> 2, tg = lane & 3;
    const int wm = (warp >> 2) * 64, wn = (warp & 3) * 32;
    const int m0 = blockIdx.y * 128, n0 = blockIdx.x * 128;

    const unsigned asB = smem_u32(As);
    const unsigned bsB = smem_u32(Bs);
    const int lrow = ((lane >> 3) & 1) * 8 + (lane & 7);
    const int lkh  = lane >> 4;
    const unsigned aoff = (unsigned)((wm + lrow) * 48 + lkh * 16);
    const unsigned boff = (unsigned)((wn + lrow) * 48 + lkh * 16);

    const int crow = tid >> 1, chalf = tid & 1;
    const __half* Asrc = A  + (size_t)(m0 + crow) * E_ + chalf * 8;
    const __half* Bsrc = Bw + (size_t)(n0 + crow) * E_ + chalf * 8;
    const unsigned cdst = (unsigned)(crow * 48 + chalf * 16);

    auto issue = [&](int c) {
        const unsigned d = cdst + (unsigned)(c % 3) * 6144u;
        cpa16(asB + d, Asrc + c * 16);
        cpa16(bsB + d, Bsrc + c * 16);
        cpacommit();
    };

    float acc[4][4][4];
#pragma unroll
    for (int i = 0; i < 4; ++i)
#pragma unroll
        for (int j = 0; j < 4; ++j)
#pragma unroll
            for (int k = 0; k < 4; ++k) acc[i][j][k] = 0.f;

    issue(0);
    issue(1);
    for (int c = 0; c < 64; ++c) {
        if (c < 63) cpawait1(); else cpawait0();
        __syncthreads();
        if (c < 62) issue(c + 2);
        const unsigned bufo = (unsigned)(c % 3) * 6144u;

        unsigned ah[4][4], bh[2][4];
#pragma unroll
        for (int mt = 0; mt < 4; ++mt)
            ldsm4(ah[mt], asB + bufo + aoff + (unsigned)mt * 768u);
#pragma unroll
        for (int p = 0; p < 2; ++p)
            ldsm4(bh[p], bsB + bufo + boff + (unsigned)p * 768u);
#pragma unroll
        for (int mt = 0; mt < 4; ++mt)
#pragma unroll
            for (int nt = 0; nt < 4; ++nt) {
                const int p = nt >> 1, sel = nt & 1;
                mma16h(acc[mt][nt], ah[mt], bh[p][sel], bh[p][sel + 2]);
            }
    }

    if (mode == 2) {
#pragma unroll
        for (int mt = 0; mt < 4; ++mt) {
            int m = m0 + wm + mt * 16 + g;
            int bi = m >> 11, n = m & 2047;
#pragma unroll
            for (int nt = 0; nt < 4; ++nt) {
                int o = n0 + wn + nt * 8 + 2 * tg;
                int h = o >> 6, d = o & 63;
                __half2 u0 = __floats2half2_rn(acc[mt][nt][0], acc[mt][nt][1]);
                __half2 u1 = __floats2half2_rn(acc[mt][nt][2], acc[mt][nt][3]);
                *(unsigned*)&Yh[(((size_t)(bi * H_ + h)) * 2048 + n) * D_ + d] = *(unsigned*)&u0;
                *(unsigned*)&Yh[(((size_t)(bi * H_ + h)) * 2048 + n + 8) * D_ + d] = *(unsigned*)&u1;
            }
        }
    } else {
#pragma unroll
        for (int mt = 0; mt < 4; ++mt) {
            int m = m0 + wm + mt * 16 + g;
#pragma unroll
            for (int nt = 0; nt < 4; ++nt) {
                int o = n0 + wn + nt * 8 + 2 * tg;
                float bx = bias[o], by = bias[o + 1];
                *(float2*)&Yf[(size_t)m * E_ + o] =
                    make_float2(acc[mt][nt][0] + bx, acc[mt][nt][1] + by);
                *(float2*)&Yf[(size_t)(m + 8) * E_ + o] =
                    make_float2(acc[mt][nt][2] + bx, acc[mt][nt][3] + by);
            }
        }
    }
}

// ---------------------------------------------------------------------------
// Attention: fp16 MMAs + fp16x2 softmax. Row sums computed by an extra
// ones-operand MMA per 16-key chunk (fp32 accumulator, no shuffles);
// numerator and denominator share identical quantized p.
// ---------------------------------------------------------------------------
__global__ __launch_bounds__(256, 2) void attn_tc()
{
    __shared__ unsigned Ks2[2][64 * 36];   // fp16 pairs, row stride 144B
    __shared__ unsigned Vs2[2][64 * 36];

    const int tid = threadIdx.x, lane = tid & 31, warp = tid >> 5;
    const int g = lane >> 2, tg = lane & 3;
    const int bh = blockIdx.y, q0 = blockIdx.x * 128;

    const unsigned* Qg = (const unsigned*)(g_Q + ((size_t)bh * N_ + q0 + warp * 16) * D_);
    unsigned qa[4][4];
#pragma unroll
    for (int c = 0; c < 4; ++c) {
        qa[c][0] = Qg[g * 32 + c * 8 + tg];
        qa[c][1] = Qg[(g + 8) * 32 + c * 8 + tg];
        qa[c][2] = Qg[g * 32 + c * 8 + tg + 4];
        qa[c][3] = Qg[(g + 8) * 32 + c * 8 + tg + 4];
    }

    float o[8][4];
#pragma unroll
    for (int i = 0; i < 8; ++i)
#pragma unroll
        for (int j = 0; j < 4; ++j) o[i][j] = 0.f;
    float lsum[4] = {0.f, 0.f, 0.f, 0.f};   // row-sum accumulator (ones-MMA)

    const __half* Kh = g_K + (size_t)bh * M_ * D_;
    const __half* Vh = g_V + (size_t)bh * M_ * D_;
    const unsigned kb0 = smem_u32(Ks2);
    const unsigned vb0 = smem_u32(Vs2);
    const int lrow = ((lane >> 3) & 1) * 8 + (lane & 7);
    const int lkh  = lane >> 4;

    const int srow = tid >> 2, si = tid & 3;
    auto issue = [&](int t, int b) {
        const __half* kr = Kh + (size_t)(t * 64 + srow) * D_;
        const __half* vr = Vh + (size_t)(t * 64 + srow) * D_;
        unsigned kd = kb0 + (unsigned)b * 9216u + (unsigned)(srow * 144 + si * 16);
        unsigned vd = vb0 + (unsigned)b * 9216u + (unsigned)(srow * 144 + si * 16);
        cpa16(kd,      kr + si * 8);
        cpa16(kd + 64, kr + si * 8 + 32);
        cpa16(vd,      vr + si * 8);
        cpa16(vd + 64, vr + si * 8 + 32);
        cpacommit();
    };

    issue(0, 0);
    for (int t = 0; t < 32; ++t) {
        cpawait0();
        __syncthreads();
        if (t < 31) issue(t + 1, (t + 1) & 1);
        const unsigned bufo = (unsigned)(t & 1) * 9216u;

        // S = Q K^T (fp16 MMA, fp32 accum); scale*log2e folded into Q
        float s[8][4];
#pragma unroll
        for (int nt = 0; nt < 8; ++nt)
#pragma unroll
            for (int j = 0; j < 4; ++j) s[nt][j] = 0.f;
#pragma unroll
        for (int c = 0; c < 4; ++c) {
#pragma unroll
            for (int p = 0; p < 4; ++p) {
                unsigned kb[4];
                ldsm4(kb, kb0 + bufo + (unsigned)((p * 16 + lrow) * 144 + c * 32 + lkh * 16));
                mma16h(s[2 * p],     qa[c], kb[0], kb[2]);
                mma16h(s[2 * p + 1], qa[c], kb[1], kb[3]);
            }
        }

        // pack S -> fp16 pairs, exp in fp16x2; results ARE the PV A-fragments.
        // Row sums accumulate via ones-operand MMA (no shuffles, fp32 accum).
        unsigned pa[4][4];
#pragma unroll
        for (int tt = 0; tt < 4; ++tt) {
            pa[tt][0] = h2ex2(packh(s[2 * tt][0],     s[2 * tt][1]));
            pa[tt][1] = h2ex2(packh(s[2 * tt][2],     s[2 * tt][3]));
            pa[tt][2] = h2ex2(packh(s[2 * tt + 1][0], s[2 * tt + 1][1]));
            pa[tt][3] = h2ex2(packh(s[2 * tt + 1][2], s[2 * tt + 1][3]));
            mma16h(lsum, pa[tt], ONESH2, ONESH2);
        }

        // O += P @ V
#pragma unroll
        for (int tt = 0; tt < 4; ++tt) {
#pragma unroll
            for (int dp = 0; dp < 4; ++dp) {
                const int j = lane >> 3, rr = lane & 7;
                int key = tt * 16 + ((j & 1) << 3) + rr;
                int dcol = dp * 16 + ((j >> 1) << 3);
                unsigned vb[4];
                ldsm4t(vb, vb0 + bufo + (unsigned)(key * 144 + dcol * 2));
                mma16h(o[2 * dp],     pa[tt], vb[0], vb[1]);
                mma16h(o[2 * dp + 1], pa[tt], vb[2], vb[3]);
            }
        }
    }

    // every thread's lsum[0]/lsum[2] hold its two row sums (all N-cols equal)
    const float inv0 = 1.f / lsum[0], inv1 = 1.f / lsum[2];
    const int bi = bh >> 4, h = bh & 15;
    const int n = q0 + warp * 16 + g;
#pragma unroll
    for (int dt = 0; dt < 8; ++dt) {
        int col = h * 64 + dt * 8 + 2 * tg;
        __half2 u0 = __floats2half2_rn(o[dt][0] * inv0, o[dt][1] * inv0);
        __half2 u1 = __floats2half2_rn(o[dt][2] * inv1, o[dt][3] * inv1);
        *(unsigned*)&g_AO[((size_t)bi * N_ + n) * E_ + col] = *(unsigned*)&u0;
        *(unsigned*)&g_AO[((size_t)bi * N_ + n + 8) * E_ + col] = *(unsigned*)&u1;
    }
}

// ---------------------------------------------------------------------------
extern "C" void kernel_launch(void* const* d_in, const int* in_sizes, int n_in,
                              void* d_out, int out_size)
{
    const float* x   = (const float*)d_in[0];
    const float* ctx = (const float*)d_in[1];
    const float* Wq  = (const float*)d_in[2];
    const float* Wk  = (const float*)d_in[3];
    const float* Wv  = (const float*)d_in[4];
    const float* Wo  = (const float*)d_in[5];
    const float* bo  = (const float*)d_in[6];
    float* out = (float*)d_out;

    __half *Qp, *Kp, *Vp, *Xh, *Ch, *AOp, *W4;
    cudaGetSymbolAddress((void**)&Qp,  g_Q);
    cudaGetSymbolAddress((void**)&Kp,  g_K);
    cudaGetSymbolAddress((void**)&Vp,  g_V);
    cudaGetSymbolAddress((void**)&Xh,  g_Xh);
    cudaGetSymbolAddress((void**)&Ch,  g_Ch);
    cudaGetSymbolAddress((void**)&AOp, g_AO);
    cudaGetSymbolAddress((void**)&W4,  g_W4);

    const int n4x = R_ * E_ / 4;
    const size_t WSZ = (size_t)E_ * E_;
    const float qs = 0.125f * 1.4426950408889634f;

    f2h<<<n4x / 256, 256>>>(x,   Xh, n4x, 1.f);
    f2h<<<n4x / 256, 256>>>(ctx, Ch, n4x, 1.f);
    f2hw<<<(4 * (int)WSZ / 4) / 256, 256>>>(Wq, Wk, Wv, Wo, W4, qs);

    dim3 ggrid(E_ / 128, R_ / 128);    // (8, 64)
    gemm_h<<<ggrid, 256>>>(Xh, W4 + 0 * WSZ, nullptr, Qp, nullptr, 2);
    gemm_h<<<ggrid, 256>>>(Ch, W4 + 1 * WSZ, nullptr, Kp, nullptr, 2);
    gemm_h<<<ggrid, 256>>>(Ch, W4 + 2 * WSZ, nullptr, Vp, nullptr, 2);
    attn_tc<<<dim3(N_ / 128, B_ * H_), 256>>>();
    gemm_h<<<ggrid, 256>>>(AOp, W4 + 3 * WSZ, out, nullptr, bo, 1);
}